// round 10
// baseline (speedup 1.0000x reference)
#include <cuda_runtime.h>
#include <cstdint>

// FFN_36867999269234 via mma.sync m16n8k16.f16 (f32 accum), zero-smem mainloop,
// COALESCED fragment ownership via K/N permutation:
//   logical k {2q,2q+1}   <- physical x-col {4q,4q+1}
//   logical k {2q+8,2q+9} <- physical x-col {4q+2,4q+3}
// (same perm applied to W1 cols; analogous perm on W2 rows / b2 for the N dim)
// => lane (g,q) loads x[g][4q..4q+3] and x[g+8][4q..4q+3] as two LDG.128 that
//    are perfectly coalesced warp-wide (512B contiguous each), stores likewise.
// L1 wavefronts per tile drop 4x vs the strided LDG.64 layout.

#define H 16
#define DM 64
#define LN_EPS 1e-5f

__device__ __forceinline__ uint32_t packh2(float lo, float hi) {
    uint32_t r;
    asm("cvt.rn.f16x2.f32 %0, %1, %2;" : "=r"(r) : "f"(hi), "f"(lo));
    return r;
}

__device__ __forceinline__ void mma_f16(float* c, const uint32_t* a, const uint32_t* b) {
    asm volatile(
        "mma.sync.aligned.m16n8k16.row.col.f32.f16.f16.f32 "
        "{%0,%1,%2,%3}, {%4,%5,%6,%7}, {%8,%9}, {%0,%1,%2,%3};"
        : "+f"(c[0]), "+f"(c[1]), "+f"(c[2]), "+f"(c[3])
        : "r"(a[0]), "r"(a[1]), "r"(a[2]), "r"(a[3]), "r"(b[0]), "r"(b[1]));
}

// LN + A1 fragment from two float4 row-chunks (xa = row g cols 4q..4q+3,
// xb = row g+8). Permuted slot map: a0/a2 = (xa.xy, xa.zw), a1/a3 = (xb).
__device__ __forceinline__ void ln_to_frag(const float4 xa, const float4 xb,
                                           uint32_t* A) {
    float s0 = (xa.x + xa.y) + (xa.z + xa.w);
    float s1 = (xb.x + xb.y) + (xb.z + xb.w);
    float q0 = fmaf(xa.x, xa.x, xa.y * xa.y) + fmaf(xa.z, xa.z, xa.w * xa.w);
    float q1 = fmaf(xb.x, xb.x, xb.y * xb.y) + fmaf(xb.z, xb.z, xb.w * xb.w);
    s0 += __shfl_xor_sync(0xFFFFFFFFu, s0, 1);
    s1 += __shfl_xor_sync(0xFFFFFFFFu, s1, 1);
    q0 += __shfl_xor_sync(0xFFFFFFFFu, q0, 1);
    q1 += __shfl_xor_sync(0xFFFFFFFFu, q1, 1);
    s0 += __shfl_xor_sync(0xFFFFFFFFu, s0, 2);
    s1 += __shfl_xor_sync(0xFFFFFFFFu, s1, 2);
    q0 += __shfl_xor_sync(0xFFFFFFFFu, q0, 2);
    q1 += __shfl_xor_sync(0xFFFFFFFFu, q1, 2);
    const float m0 = s0 * (1.f / H);
    const float m1 = s1 * (1.f / H);
    const float r0 = rsqrtf(q0 * (1.f / H) - m0 * m0 + LN_EPS);
    const float r1 = rsqrtf(q1 * (1.f / H) - m1 * m1 + LN_EPS);
    A[0] = packh2((xa.x - m0) * r0, (xa.y - m0) * r0);
    A[1] = packh2((xb.x - m1) * r1, (xb.y - m1) * r1);
    A[2] = packh2((xa.z - m0) * r0, (xa.w - m0) * r0);
    A[3] = packh2((xb.z - m1) * r1, (xb.w - m1) * r1);
}

__global__ __launch_bounds__(128, 4) void ffn_mma(
    const float* __restrict__ x,
    const float* __restrict__ gamma,
    const float* __restrict__ beta,
    const float* __restrict__ w1,   // [DM, H]
    const float* __restrict__ b1,   // [DM]
    const float* __restrict__ w2,   // [H, DM]
    const float* __restrict__ b2,   // [H]
    float* __restrict__ out,
    int ntok)
{
    __shared__ float2 c1bs[8][4];   // folded b1, [h-ntile j][q] = h cols 2q,2q+1
    __shared__ float2 c2bs[2][4];   // b2 (physical), [jn][q] = cols 4q+2jn, +1

    const int tid  = threadIdx.x;
    const int wid  = tid >> 5;
    const int lane = tid & 31;
    const int g = lane >> 2;
    const int q = lane & 3;

    // ---- B1 fragments: logical k slots {2q,2q+1}/{2q+8,2q+9} come from
    //      physical x cols {4q,4q+1}/{4q+2,4q+3} -> same perm on w1 cols ----
    uint32_t B1[8][2];
    #pragma unroll
    for (int j = 0; j < 8; j++) {
        const float* wr = w1 + (8 * j + g) * H;
        B1[j][0] = packh2(wr[4 * q]     * gamma[4 * q],     wr[4 * q + 1] * gamma[4 * q + 1]);
        B1[j][1] = packh2(wr[4 * q + 2] * gamma[4 * q + 2], wr[4 * q + 3] * gamma[4 * q + 3]);
    }
    // ---- B2 fragments: logical out-col n=8*jn+g -> physical w2 row
    //      rn = 4*(g>>1) + 2*jn + (g&1). k (h dim) unpermuted. ----
    uint32_t B2[4][2][2];
    #pragma unroll
    for (int s = 0; s < 4; s++)
        #pragma unroll
        for (int jn = 0; jn < 2; jn++) {
            const int rn = 4 * (g >> 1) + 2 * jn + (g & 1);
            const float* wr = w2 + rn * DM + 16 * s;
            B2[s][jn][0] = packh2(wr[2 * q],     wr[2 * q + 1]);
            B2[s][jn][1] = packh2(wr[2 * q + 8], wr[2 * q + 9]);
        }

    // ---- bias LUTs ----
    if (tid < 32) {
        int j = tid >> 2, qq = tid & 3;
        float a0 = b1[8 * j + 2 * qq], a1 = b1[8 * j + 2 * qq + 1];
        #pragma unroll
        for (int k = 0; k < H; k++) {
            a0 = fmaf(w1[(8 * j + 2 * qq) * H + k],     beta[k], a0);
            a1 = fmaf(w1[(8 * j + 2 * qq + 1) * H + k], beta[k], a1);
        }
        c1bs[j][qq] = make_float2(a0, a1);
    }
    if (tid < 8) {
        int jn = tid >> 2, qq = tid & 3;  // note: only qq 0,1 here; fill all 4 below
    }
    if (tid < 8) {
        int jn = (tid >> 2) & 1, qq = tid & 3;
        c2bs[jn][qq] = make_float2(b2[4 * qq + 2 * jn], b2[4 * qq + 2 * jn + 1]);
    }
    __syncthreads();

    // ---------------- pipelined token loop: 16 tokens/warp-tile ----------------
    const int ntiles = ntok >> 4;             // ntok multiple of 16
    const int wstep  = gridDim.x * 4;
    const int wt0    = blockIdx.x * 4 + wid;
    if (wt0 >= ntiles) return;

    const long long e0 = (long long)g * H + 4 * q;          // row g,   cols 4q..4q+3
    const long long e1 = (long long)(g + 8) * H + 4 * q;    // row g+8

    auto loadfrag = [&](int wt, float4& a, float4& b) {
        const float* p = x + ((long long)wt << 4) * H;
        a = *(const float4*)(p + e0);
        b = *(const float4*)(p + e1);
    };

    float4 va, vb, na, nb;
    loadfrag(wt0, va, vb);
    {
        int w1t = wt0 + wstep < ntiles ? wt0 + wstep : wt0;
        loadfrag(w1t, na, nb);
    }
    uint32_t A1[4];
    ln_to_frag(va, vb, A1);

    for (int wt = wt0; wt < ntiles; wt += wstep) {
        // ---- prefetch x(i+2) ----
        float4 pa, pb;
        {
            int w2t = wt + 2 * wstep;
            if (w2t >= ntiles) w2t = wt;
            loadfrag(w2t, pa, pb);
        }

        // ---- MMA1(i): C1[16x64] = y·W1g^T + b1fold ----
        float C1[8][4];
        #pragma unroll
        for (int j = 0; j < 8; j++) {
            const float2 b = c1bs[j][q];
            C1[j][0] = b.x; C1[j][1] = b.y; C1[j][2] = b.x; C1[j][3] = b.y;
            mma_f16(C1[j], A1, B1[j]);
        }

        // ---- LN(i+1) overlapped with MMA1 latency ----
        uint32_t A1n[4];
        ln_to_frag(na, nb, A1n);

        // ---- MMA2(i): C2 = relu(C1)·W2^T + b2 (C->A frag identity) ----
        float C2[2][4];
        #pragma unroll
        for (int jn = 0; jn < 2; jn++) {
            const float2 b = c2bs[jn][q];
            C2[jn][0] = b.x; C2[jn][1] = b.y; C2[jn][2] = b.x; C2[jn][3] = b.y;
        }
        #pragma unroll
        for (int s = 0; s < 4; s++) {
            uint32_t A2[4];
            A2[0] = packh2(fmaxf(C1[2 * s][0], 0.f),     fmaxf(C1[2 * s][1], 0.f));
            A2[1] = packh2(fmaxf(C1[2 * s][2], 0.f),     fmaxf(C1[2 * s][3], 0.f));
            A2[2] = packh2(fmaxf(C1[2 * s + 1][0], 0.f), fmaxf(C1[2 * s + 1][1], 0.f));
            A2[3] = packh2(fmaxf(C1[2 * s + 1][2], 0.f), fmaxf(C1[2 * s + 1][3], 0.f));
            mma_f16(C2[0], A2, B2[s][0]);
            mma_f16(C2[1], A2, B2[s][1]);
        }

        // ---- residual + coalesced STG.128 (physical col layout) ----
        // lane owns physical out cols 4q..4q+3 = logical {2q,2q+1} (jn=0) ++
        // logical {2q+8,2q+9} (jn=1): (C2[0][0],C2[0][1],C2[1][0],C2[1][1])
        {
            float* p = out + ((long long)wt << 4) * H;
            *(float4*)(p + e0) = make_float4(C2[0][0] + va.x, C2[0][1] + va.y,
                                             C2[1][0] + va.z, C2[1][1] + va.w);
            *(float4*)(p + e1) = make_float4(C2[0][2] + vb.x, C2[0][3] + vb.y,
                                             C2[1][2] + vb.z, C2[1][3] + vb.w);
        }

        // ---- rotate pipeline state ----
        va = na; vb = nb;
        na = pa; nb = pb;
        A1[0] = A1n[0]; A1[1] = A1n[1]; A1[2] = A1n[2]; A1[3] = A1n[3];
    }
}

extern "C" void kernel_launch(void* const* d_in, const int* in_sizes, int n_in,
                              void* d_out, int out_size) {
    const float* x     = (const float*)d_in[0];
    const float* gamma = (const float*)d_in[1];
    const float* beta  = (const float*)d_in[2];
    const float* w1    = (const float*)d_in[3];
    const float* b1    = (const float*)d_in[4];
    const float* w2    = (const float*)d_in[5];
    const float* b2    = (const float*)d_in[6];
    float* out         = (float*)d_out;

    const int ntok = in_sizes[0] / H;   // 1,048,576 (multiple of 16)
    const int threads = 128;            // 4 warps x 16 tokens
    int blocks = 148 * 4;               // persistent grid-stride
    ffn_mma<<<blocks, threads>>>(x, gamma, beta, w1, b1, w2, b2, out, ntok);
}